// round 7
// baseline (speedup 1.0000x reference)
#include <cuda_runtime.h>
#include <cstddef>

#define BSZ 8
#define SEQLEN 2048
#define VOCAB 32000
#define BOS 1
#define V4 (VOCAB / 4)               // 8000 float4 per row
#define FILL_BLOCKS (BSZ * SEQLEN)   // 16384 rows, one block each
#define THREADS 256

// Global scratch (allocation-free rule: __device__ globals only)
__device__ int g_hist[BSZ][VOCAB];   // 1 MB
__device__ int g_pred[BSZ];
__device__ int g_ready[BSZ];         // 0-init; stale 1 across graph replays is
                                     // benign: same inputs -> same pred value.

// ---------------------------------------------------------------------------
// Single fused kernel:
//   blocks [0, 8)             : per-batch majority -> g_pred[b], flag ready
//   blocks [8, 8+FILL_BLOCKS) : write one (b,s) row of -6, then patch own
//                               pred element with +6 (poll ready flag first).
// Majority blocks are wave-1 resident (lowest block ids) and finish in a few
// microseconds; fill blocks take ~20us/row, so the poll is ~always satisfied.
// ---------------------------------------------------------------------------
__global__ void fused_kernel(const int* __restrict__ ids,
                             float4* __restrict__ out) {
    const int bid = blockIdx.x;
    const int t   = threadIdx.x;

    if (bid >= BSZ) {
        // ---- streaming fill: pure -6, plain STG.128 (no cache hints!) ----
        const int r = bid - BSZ;          // row index in [0, 16384)
        const int b = r >> 11;            // batch = r / SEQLEN
        const float4 neg = make_float4(-6.0f, -6.0f, -6.0f, -6.0f);
        float4* __restrict__ dst = out + (size_t)r * V4;

        for (int i = t; i < V4; i += THREADS) {
            dst[i] = neg;
        }

        __syncthreads();                  // order own -6 stores before patch

        if (t == 0) {
            // wait for this batch's pred (nearly always already set)
            while (atomicAdd(&g_ready[b], 0) == 0) { }
            __threadfence();
            int p = *(volatile int*)&g_pred[b];
            ((float*)dst)[p] = 6.0f;      // overwrite pred column with +6
        }
        return;
    }

    // ---- majority for batch row b = bid ----
    const int b = bid;
    int* __restrict__ hist = g_hist[b];

    // zero histogram row
    for (int v = t; v < VOCAB; v += THREADS) hist[v] = 0;
    __syncthreads();

    // accumulate valid tokens (exclude pad=0 and BOS=1)
    const int* row = ids + (size_t)b * SEQLEN;
    for (int s = t; s < SEQLEN; s += THREADS) {
        int tok = row[s];
        if (tok != 0 && tok != BOS) atomicAdd(&hist[tok], 1);
    }
    __syncthreads();

    // argmax, tie -> lowest index: key = (count<<15) | (32767 - v)
    __shared__ int best;
    if (t == 0) best = 0;
    __syncthreads();

    int lb = 0;
    for (int v = t; v < VOCAB; v += THREADS) {
        int key = (hist[v] << 15) | (32767 - v);
        if (key > lb) lb = key;
    }
    atomicMax(&best, lb);
    __syncthreads();

    if (t == 0) {
        int cnt = best >> 15;
        int v = 32767 - (best & 32767);
        g_pred[b] = (cnt > 0) ? v : BOS;  // no valid tokens -> BOS
        __threadfence();                  // pred visible before flag
        atomicExch(&g_ready[b], 1);
    }
}

extern "C" void kernel_launch(void* const* d_in, const int* in_sizes, int n_in,
                              void* d_out, int out_size) {
    (void)in_sizes; (void)n_in; (void)out_size;
    const int* ids = (const int*)d_in[0];

    fused_kernel<<<BSZ + FILL_BLOCKS, THREADS>>>(ids, (float4*)d_out);
}

// round 8
// speedup vs baseline: 1.4236x; 1.4236x over previous
#include <cuda_runtime.h>
#include <cstddef>

#define BSZ 8
#define SEQLEN 2048
#define VOCAB 32000
#define BOS 1
#define V4 (VOCAB / 4)               // 8000 float4 per row
#define FILL_BLOCKS (BSZ * SEQLEN)   // 16384 rows, one block each
#define THREADS 256

// Global scratch (allocation-free rule: __device__ globals only)
__device__ int g_hist[BSZ][VOCAB];   // 1 MB
__device__ int g_pred[BSZ];

// ---------------------------------------------------------------------------
// Fused kernel (UNCHANGED from R5 winner — do not touch the store stream):
//   blocks [0, 8)             : per-batch majority -> g_pred[b]
//   blocks [8, 8+FILL_BLOCKS) : stream one (b,s) row of pure -6
// Plain STG.128 (R4 lesson: no cache hints; R6 lesson: no sync/atomic ops
// mixed into the streaming-store kernel).
// ---------------------------------------------------------------------------
__global__ void fused_kernel(const int* __restrict__ ids,
                             float4* __restrict__ out) {
    const int bid = blockIdx.x;
    const int t   = threadIdx.x;

    if (bid >= BSZ) {
        // ---- streaming fill: pure -6, plain vectorized stores ----
        const int r = bid - BSZ;     // row index in [0, 16384)
        const float4 neg = make_float4(-6.0f, -6.0f, -6.0f, -6.0f);
        float4* __restrict__ dst = out + (size_t)r * V4;

        for (int i = t; i < V4; i += THREADS) {
            dst[i] = neg;
        }
        return;
    }

    // ---- majority for batch row b = bid ----
    const int b = bid;
    int* __restrict__ hist = g_hist[b];

    // zero histogram row
    for (int v = t; v < VOCAB; v += THREADS) hist[v] = 0;
    __syncthreads();

    // accumulate valid tokens (exclude pad=0 and BOS=1)
    const int* row = ids + (size_t)b * SEQLEN;
    for (int s = t; s < SEQLEN; s += THREADS) {
        int tok = row[s];
        if (tok != 0 && tok != BOS) atomicAdd(&hist[tok], 1);
    }
    __syncthreads();

    // argmax, tie -> lowest index: key = (count<<15) | (32767 - v)
    __shared__ int best;
    if (t == 0) best = 0;
    __syncthreads();

    int lb = 0;
    for (int v = t; v < VOCAB; v += THREADS) {
        int key = (hist[v] << 15) | (32767 - v);
        if (key > lb) lb = key;
    }
    atomicMax(&best, lb);
    __syncthreads();

    if (t == 0) {
        int cnt = best >> 15;
        int v = 32767 - (best & 32767);
        g_pred[b] = (cnt > 0) ? v : BOS;  // no valid tokens -> BOS
    }
}

// ---------------------------------------------------------------------------
// Patch kernel v2: for each of the 16384 (b,s) rows, rewrite the aligned
// 32-byte sector containing the pred element (7 x -6, 1 x +6) as two
// STG.128 -> full-sector writes, no DRAM read-modify-write.
// 32 blocks x 512 threads = one row per thread.
// ---------------------------------------------------------------------------
__global__ void patch_kernel(float* __restrict__ out) {
    const int idx = blockIdx.x * 512 + threadIdx.x;    // [0, 16384)
    const int b = idx >> 11;                           // / SEQLEN
    const int p = g_pred[b];

    const int base = p & ~7;                           // 8-float (32B) window
    const int c    = p & 7;                            // slot within window

    float4 lo = make_float4(-6.0f, -6.0f, -6.0f, -6.0f);
    float4 hi = lo;
    // set +6 in the right slot
    if      (c == 0) lo.x = 6.0f;
    else if (c == 1) lo.y = 6.0f;
    else if (c == 2) lo.z = 6.0f;
    else if (c == 3) lo.w = 6.0f;
    else if (c == 4) hi.x = 6.0f;
    else if (c == 5) hi.y = 6.0f;
    else if (c == 6) hi.z = 6.0f;
    else             hi.w = 6.0f;

    // row start (idx * 128000 B) is 32B-aligned; base*4 is 32B-aligned.
    float4* dst = (float4*)(out + (size_t)idx * VOCAB + base);
    dst[0] = lo;
    dst[1] = hi;
}

extern "C" void kernel_launch(void* const* d_in, const int* in_sizes, int n_in,
                              void* d_out, int out_size) {
    (void)in_sizes; (void)n_in; (void)out_size;
    const int* ids = (const int*)d_in[0];

    fused_kernel<<<BSZ + FILL_BLOCKS, THREADS>>>(ids, (float4*)d_out);
    patch_kernel<<<FILL_BLOCKS / 512, 512>>>((float*)d_out);
}

// round 10
// speedup vs baseline: 1.4427x; 1.0134x over previous
#include <cuda_runtime.h>
#include <cstddef>

#define BSZ 8
#define SEQLEN 2048
#define VOCAB 32000
#define BOS 1
#define V4 (VOCAB / 4)               // 8000 float4 per row
#define FILL_BLOCKS (BSZ * SEQLEN)   // 16384 rows, one block each
#define THREADS 256

// Global scratch (allocation-free rule: __device__ globals only)
__device__ int g_hist[BSZ][VOCAB];   // 1 MB
__device__ int g_pred[BSZ];

// ---------------------------------------------------------------------------
// Kernel A: per-batch majority. Triggers programmatic launch completion at
// entry so the fill grid launches and streams concurrently.
// ---------------------------------------------------------------------------
__global__ __launch_bounds__(1024) void majority_kernel(const int* __restrict__ ids) {
#if __CUDA_ARCH__ >= 900
    cudaTriggerProgrammaticLaunchCompletion();   // let fill grid launch now
#endif
    const int b = blockIdx.x;
    const int t = threadIdx.x;
    int* __restrict__ hist = g_hist[b];

    // zero histogram row
    for (int v = t; v < VOCAB; v += 1024) hist[v] = 0;
    __syncthreads();

    // accumulate valid tokens (exclude pad=0 and BOS=1)
    const int* row = ids + (size_t)b * SEQLEN;
    for (int s = t; s < SEQLEN; s += 1024) {
        int tok = row[s];
        if (tok != 0 && tok != BOS) atomicAdd(&hist[tok], 1);
    }
    __syncthreads();

    // argmax, tie -> lowest index: key = (count<<15) | (32767 - v)
    __shared__ int best;
    if (t == 0) best = 0;
    __syncthreads();

    int lb = 0;
    for (int v = t; v < VOCAB; v += 1024) {
        int key = (hist[v] << 15) | (32767 - v);
        if (key > lb) lb = key;
    }
    atomicMax(&best, lb);
    __syncthreads();

    if (t == 0) {
        int cnt = best >> 15;
        int v = 32767 - (best & 32767);
        g_pred[b] = (cnt > 0) ? v : BOS;  // no valid tokens -> BOS
    }
}

// ---------------------------------------------------------------------------
// Kernel B: streaming fill, one (b,s) row per block. Pure -6 STG.128 stream
// (no cache hints, no atomics, no fences), then a HW-backed PDL wait for the
// majority grid, then thread 0 rewrites the aligned 32B sector holding the
// pred element (full-sector write, no DRAM RMW).
// ---------------------------------------------------------------------------
__global__ __launch_bounds__(THREADS) void fill_kernel(float4* __restrict__ out) {
    const int r = blockIdx.x;            // row index in [0, 16384)
    const int t = threadIdx.x;
    const int b = r >> 11;               // batch = r / SEQLEN

    const float4 neg = make_float4(-6.0f, -6.0f, -6.0f, -6.0f);
    float4* __restrict__ dst = out + (size_t)r * V4;

    for (int i = t; i < V4; i += THREADS) {
        dst[i] = neg;
    }

#if __CUDA_ARCH__ >= 900
    cudaGridDependencySynchronize();     // majority grid complete + visible
#endif
    __syncthreads();                     // order own -6 stores before patch

    if (t == 0) {
        const int p    = g_pred[b];
        const int base = p & ~7;         // 8-float (32B) aligned window
        const int c    = p & 7;

        float4 lo = neg, hi = neg;
        if      (c == 0) lo.x = 6.0f;
        else if (c == 1) lo.y = 6.0f;
        else if (c == 2) lo.z = 6.0f;
        else if (c == 3) lo.w = 6.0f;
        else if (c == 4) hi.x = 6.0f;
        else if (c == 5) hi.y = 6.0f;
        else if (c == 6) hi.z = 6.0f;
        else             hi.w = 6.0f;

        // row start (r * 128000B) and base*4 are 32B-aligned -> full sector
        float4* p4 = (float4*)((float*)dst + base);
        p4[0] = lo;
        p4[1] = hi;
    }
}

extern "C" void kernel_launch(void* const* d_in, const int* in_sizes, int n_in,
                              void* d_out, int out_size) {
    (void)in_sizes; (void)n_in; (void)out_size;
    const int* ids = (const int*)d_in[0];

    majority_kernel<<<BSZ, 1024>>>(ids);

    // Fill with programmatic dependent launch: overlaps with majority_kernel,
    // each block waits via cudaGridDependencySynchronize before patching.
    cudaLaunchConfig_t cfg = {};
    cfg.gridDim  = dim3(FILL_BLOCKS, 1, 1);
    cfg.blockDim = dim3(THREADS, 1, 1);
    cfg.dynamicSmemBytes = 0;
    cfg.stream = 0;   // same (legacy) stream the harness captures

    cudaLaunchAttribute attr[1];
    attr[0].id = cudaLaunchAttributeProgrammaticStreamSerialization;
    attr[0].val.programmaticStreamSerializationAllowed = 1;
    cfg.attrs = attr;
    cfg.numAttrs = 1;

    cudaLaunchKernelEx(&cfg, fill_kernel, (float4*)d_out);
}